// round 8
// baseline (speedup 1.0000x reference)
#include <cuda_runtime.h>
#include <cuda_fp16.h>
#include <cstdint>

// Problem constants
constexpr int BATCH = 64;
constexpr int IN    = 8192;
constexpr int OUT   = 8192;

// Tiling: CTA = 64 out rows x full K, grid 128. KC=128, 16 warps (1m x 2n x 8k).
constexpr int TO      = 64;
constexpr int KC      = 128;
constexpr int NCH     = IN / KC;     // 64
constexpr int THREADS = 512;

constexpr int XS = 136;              // x smem stride (halves): 272B rows, ldsm conflict-free
constexpr int WS = 136;

constexpr int X_STAGE_B = BATCH * XS * 2;   // 17408
constexpr int W_BUF_B   = TO * WS * 2;      // 17408
constexpr int X_STAGES  = 4;

constexpr int SMEM_X_OFF    = 0;
constexpr int SMEM_W_OFF    = X_STAGES * X_STAGE_B;        // 69632
constexpr int SMEM_PT_OFF   = SMEM_W_OFF + 2 * W_BUF_B;    // 104448 (pair LUT, 64KB)
constexpr int SMEM_LR_OFF   = SMEM_PT_OFF + TO * 256 * 4;  // 169984 (raw LUT rows, 2KB)
constexpr int SMEM_FLAG_OFF = SMEM_LR_OFF + TO * 16 * 2;   // 172032
constexpr int SMEM_TOTAL    = SMEM_FLAG_OFF + 16;          // 172048

__device__ __half g_x16[BATCH * IN];   // x as fp16

__device__ __forceinline__ void cp_async16(unsigned smem_dst, const void* gmem_src) {
    asm volatile("cp.async.cg.shared.global [%0], [%1], 16;\n" :: "r"(smem_dst), "l"(gmem_src));
}
__device__ __forceinline__ void cp_commit() {
    asm volatile("cp.async.commit_group;\n" ::: "memory");
}
template <int N>
__device__ __forceinline__ void cp_wait() {
    asm volatile("cp.async.wait_group %0;\n" :: "n"(N) : "memory");
}
__device__ __forceinline__ void ldsm_x4(unsigned& r0, unsigned& r1, unsigned& r2, unsigned& r3,
                                        unsigned addr) {
    asm volatile("ldmatrix.sync.aligned.m8n8.x4.shared.b16 {%0,%1,%2,%3}, [%4];\n"
                 : "=r"(r0), "=r"(r1), "=r"(r2), "=r"(r3) : "r"(addr));
}
__device__ __forceinline__ void mma_m16n8k16(float& c0, float& c1, float& c2, float& c3,
                                             unsigned a0, unsigned a1, unsigned a2, unsigned a3,
                                             unsigned b0, unsigned b1) {
    asm volatile(
        "mma.sync.aligned.m16n8k16.row.col.f32.f16.f16.f32 "
        "{%0,%1,%2,%3}, {%4,%5,%6,%7}, {%8,%9}, {%0,%1,%2,%3};\n"
        : "+f"(c0), "+f"(c1), "+f"(c2), "+f"(c3)
        : "r"(a0), "r"(a1), "r"(a2), "r"(a3), "r"(b0), "r"(b1));
}

// probe: lut words reinterpreted as f32 land in (1e-4,1) when stored f32 (N(0,0.05));
// packed half pairs reinterpret to < ~3e-5. Ballot over 32 words.
__device__ __forceinline__ int probe_f32(const unsigned* lut_words, int lane) {
    float a = fabsf(__uint_as_float(lut_words[lane]));
    unsigned m = __ballot_sync(0xffffffffu, a > 1e-4f && a < 1.0f);
    return __popc(m) >= 16;
}

// ---- launch 1: x -> fp16 scratch ----
__global__ void xconv_kernel(const void* __restrict__ xp,
                             const unsigned* __restrict__ lut_words) {
    __shared__ int flag_s;
    const int tid = threadIdx.x;
    if (tid < 32) {
        int f = probe_f32(lut_words, tid);
        if (tid == 0) flag_s = f;
    }
    __syncthreads();
    const int i = (blockIdx.x * blockDim.x + tid) * 4;
    if (flag_s) {
        float4 v = *reinterpret_cast<const float4*>(reinterpret_cast<const float*>(xp) + i);
        *reinterpret_cast<__half2*>(g_x16 + i)     = __floats2half2_rn(v.x, v.y);
        *reinterpret_cast<__half2*>(g_x16 + i + 2) = __floats2half2_rn(v.z, v.w);
    } else {
        *reinterpret_cast<uint2*>(g_x16 + i) =
            *reinterpret_cast<const uint2*>(reinterpret_cast<const __half*>(xp) + i);
    }
}

// ---- launch 2: main ----
__global__ __launch_bounds__(THREADS, 1)
void anyprec_linear_kernel(const int*  __restrict__ qw,
                           const void* __restrict__ lutp,
                           void*       __restrict__ outp) {
    extern __shared__ char smem[];
    unsigned* pt_u   = reinterpret_cast<unsigned*>(smem + SMEM_PT_OFF);
    __half*   lr_s   = reinterpret_cast<__half*>(smem + SMEM_LR_OFF);
    int*      flag_p = reinterpret_cast<int*>(smem + SMEM_FLAG_OFF);
    const unsigned smem_u = (unsigned)__cvta_generic_to_shared(smem);
    const unsigned x_u    = smem_u + SMEM_X_OFF;
    const unsigned w_u    = smem_u + SMEM_W_OFF;

    const int tid  = threadIdx.x;
    const int lane = tid & 31;
    const int wid  = tid >> 5;
    const int rblk = blockIdx.x * TO;

    if (tid < 32) {
        int f = probe_f32(reinterpret_cast<const unsigned*>(lutp), lane);
        if (lane == 0) *flag_p = f;
    }

    // ---- x prefetch mapping: thread -> (row 0..63, seg 0..7), 2x16B per chunk ----
    const int xr = tid >> 3, xs8 = tid & 7;
    const __half* xg_base = g_x16 + (size_t)xr * IN + xs8 * 8;
    const unsigned x_dst  = x_u + xr * 272 + xs8 * 16;
    auto xfetch = [&](int c) {
        const unsigned d = x_dst + (c & 3) * X_STAGE_B;
        const __half* s = xg_base + c * KC;
        cp_async16(d,       s);
        cp_async16(d + 128, s + 64);   // seg+8: +8*16B dst, +64 halves src
    };
    xfetch(0); cp_commit();
    xfetch(1); cp_commit();
    xfetch(2); cp_commit();

    // ---- qw mapping: thread -> (row 0..63, seg 0..7); 4 strided int4 per chunk ----
    const int drow = tid >> 3, dseg = tid & 7;
    const int4* qptr = reinterpret_cast<const int4*>(
        qw + (size_t)(rblk + drow) * IN + dseg * 4);   // + c*32 (int4 units) per chunk
    int4 qq[4];
#pragma unroll
    for (int i = 0; i < 4; i++) qq[i] = __ldcs(qptr + i * 8);   // chunk 0

    __syncthreads();
    const bool F32 = (*flag_p != 0);

    // LUT rows -> smem (as half)
    if (F32) {
        const float* lf = reinterpret_cast<const float*>(lutp);
        for (int i = tid; i < TO * 16; i += THREADS)
            lr_s[i] = __float2half_rn(lf[(size_t)rblk * 16 + i]);
    } else {
        const __half* lh = reinterpret_cast<const __half*>(lutp);
        for (int i = tid; i < TO * 16; i += THREADS)
            lr_s[i] = lh[(size_t)rblk * 16 + i];
    }
    __syncthreads();

    // Build pair LUT: ptab[row][(a<<4)|b] = halves (lut[row][a], lut[row][b])
    for (int idx = tid; idx < TO * 256; idx += THREADS) {
        const int row = idx >> 8, pr = idx & 255;
        unsigned lo = __half_as_ushort(lr_s[row * 16 + (pr >> 4)]);
        unsigned hi = __half_as_ushort(lr_s[row * 16 + (pr & 15)]);
        pt_u[idx] = lo | (hi << 16);
    }
    const unsigned* ptrow = pt_u + (drow << 8);

    // ---- warp decomposition: 1m x 2n x 8k ----
    const int ni = wid >> 3;          // 0..1
    const int ki = wid & 7;           // 0..7
    const int q = lane >> 3, rr = lane & 7, g = lane >> 2, t = lane & 3;

    unsigned a_off[4], b_off[2];
#pragma unroll
    for (int mt = 0; mt < 4; mt++)
        a_off[mt] = (mt * 16 + ((q & 1) << 3) + rr) * 272
                    + (ki * 16 + ((q >> 1) << 3)) * 2;
#pragma unroll
    for (int nt = 0; nt < 2; nt++)
        b_off[nt] = (ni * 32 + nt * 16 + ((q >> 1) << 3) + rr) * 272
                    + (ki * 16 + ((q & 1) << 3)) * 2;

    float acc[4][4][4];
#pragma unroll
    for (int mt = 0; mt < 4; mt++)
#pragma unroll
        for (int j = 0; j < 4; j++)
#pragma unroll
            for (int e = 0; e < 4; e++) acc[mt][j][e] = 0.0f;

    const unsigned w_st_base = w_u + drow * 272 + dseg * 8;

#pragma unroll 2
    for (int c = 0; c < NCH; c++) {
        cp_wait<2>();          // x stage c landed (this thread's part)
        __syncthreads();       // all parts visible; prior chunk's ldsm retired
                               // (also orders ptab build before first dequant)
        if (c + 3 < NCH) xfetch(c + 3);
        cp_commit();           // commit every iter keeps the wait<2> invariant

        // ---- dequant via pair LUT: 8 LDS.32 + 4 STS.64 ----
#pragma unroll
        for (int i = 0; i < 4; i++) {
            const int4 qa = qq[i];
            unsigned p0 = ptrow[((qa.x & 15) << 4) | (qa.y & 15)];
            unsigned p1 = ptrow[((qa.z & 15) << 4) | (qa.w & 15)];
            asm volatile("st.shared.v2.b32 [%0], {%1,%2};" ::
                         "r"(w_st_base + (c & 1) * W_BUF_B + i * 64),  // (dseg+8i)*8
                         "r"(p0), "r"(p1) : "memory");
        }
        // reload qw for next chunk (latency hidden behind sync2 + ldsm + mma)
        if (c + 1 < NCH) {
#pragma unroll
            for (int i = 0; i < 4; i++) qq[i] = __ldcs(qptr + (c + 1) * 32 + i * 8);
        }
        __syncthreads();       // w tile visible

        // ---- mma: 6 ldmatrix.x4 + 16 mma ----
        const unsigned xa = x_u + (c & 3) * X_STAGE_B;
        const unsigned wa = w_u + (c & 1) * W_BUF_B;
        unsigned bf[2][4];
#pragma unroll
        for (int nt = 0; nt < 2; nt++)
            ldsm_x4(bf[nt][0], bf[nt][1], bf[nt][2], bf[nt][3], wa + b_off[nt]);
#pragma unroll
        for (int mt = 0; mt < 4; mt++) {
            unsigned a0, a1, a2, a3;
            ldsm_x4(a0, a1, a2, a3, xa + a_off[mt]);
#pragma unroll
            for (int j = 0; j < 4; j++) {
                const int nt = j >> 1, sub = j & 1;
                mma_m16n8k16(acc[mt][j][0], acc[mt][j][1], acc[mt][j][2], acc[mt][j][3],
                             a0, a1, a2, a3, bf[nt][sub * 2], bf[nt][sub * 2 + 1]);
            }
        }
    }

    // ---- epilogue: 8-way k-split reduction, two 32-row passes ----
    float* psum = reinterpret_cast<float*>(smem);   // [8][32][64] f32 = 64KB (overlays x)
#pragma unroll
    for (int p = 0; p < 2; p++) {
        __syncthreads();
#pragma unroll
        for (int mh = 0; mh < 2; mh++) {
            const int mt = p * 2 + mh;
#pragma unroll
            for (int j = 0; j < 4; j++) {
                const int m_loc = mh * 16 + g;
                const int n = ni * 32 + j * 8 + t * 2;
                *reinterpret_cast<float2*>(psum + ki * 2048 + m_loc * 64 + n) =
                    make_float2(acc[mt][j][0], acc[mt][j][1]);
                *reinterpret_cast<float2*>(psum + ki * 2048 + (m_loc + 8) * 64 + n) =
                    make_float2(acc[mt][j][2], acc[mt][j][3]);
            }
        }
        __syncthreads();

        const int base = tid * 4;           // 512 threads x 4 outputs = 32x64
        const int m_loc = base >> 6;
        const int n0 = base & 63;
        float4 s = *reinterpret_cast<const float4*>(psum + m_loc * 64 + n0);
#pragma unroll
        for (int pl = 1; pl < 8; pl++) {
            float4 v = *reinterpret_cast<const float4*>(psum + pl * 2048 + m_loc * 64 + n0);
            s.x += v.x; s.y += v.y; s.z += v.z; s.w += v.w;
        }
        const int m = p * 32 + m_loc;
        __half2 lo = __floats2half2_rn(s.x, s.y);
        __half2 hi = __floats2half2_rn(s.z, s.w);
        if (F32) {
            float4 o;
            o.x = __half2float(__low2half(lo)); o.y = __half2float(__high2half(lo));
            o.z = __half2float(__low2half(hi)); o.w = __half2float(__high2half(hi));
            *reinterpret_cast<float4*>(reinterpret_cast<float*>(outp)
                                       + (size_t)m * OUT + rblk + n0) = o;
        } else {
            uint2 o;
            o.x = *reinterpret_cast<unsigned*>(&lo);
            o.y = *reinterpret_cast<unsigned*>(&hi);
            *reinterpret_cast<uint2*>(reinterpret_cast<__half*>(outp)
                                      + (size_t)m * OUT + rblk + n0) = o;
        }
    }
}

extern "C" void kernel_launch(void* const* d_in, const int* in_sizes, int n_in,
                              void* d_out, int out_size) {
    // Identify inputs by element count: x 524288, qweight 67108864, lut 131072
    const void* x = nullptr; const int* qw = nullptr; const void* lut = nullptr;
    for (int i = 0; i < n_in; i++) {
        if (in_sizes[i] == BATCH * IN)     x   = d_in[i];
        else if (in_sizes[i] == OUT * IN)  qw  = (const int*)d_in[i];
        else if (in_sizes[i] == OUT * 16)  lut = d_in[i];
    }

    cudaFuncSetAttribute(anyprec_linear_kernel,
                         cudaFuncAttributeMaxDynamicSharedMemorySize, SMEM_TOTAL);

    xconv_kernel<<<BATCH * IN / 4 / 256, 256>>>(x, reinterpret_cast<const unsigned*>(lut));
    anyprec_linear_kernel<<<OUT / TO, THREADS, SMEM_TOTAL>>>(qw, lut, d_out);
}

// round 9
// speedup vs baseline: 1.1219x; 1.1219x over previous
#include <cuda_runtime.h>
#include <cuda_fp16.h>
#include <cstdint>

// Problem constants
constexpr int BATCH = 64;
constexpr int IN    = 8192;
constexpr int OUT   = 8192;

// Tiling: CTA = 64 out rows x full K, grid 128.
constexpr int TO      = 64;
constexpr int KC      = 64;
constexpr int NCH     = IN / KC;     // 128
constexpr int THREADS = 512;         // 16 warps: 2m x 2n x 4k

constexpr int XS = 72;               // x smem stride (halves) - conflict-free ldsm
constexpr int WS = 72;               // w smem stride (halves)

constexpr int X_STAGE_B = TO * XS * 2;            // 9216 B
constexpr int W_BUF_B   = TO * WS * 2;            // 9216 B
constexpr int X_STAGES  = 4;

constexpr int SMEM_X_OFF   = 0;
constexpr int SMEM_W_OFF   = X_STAGES * X_STAGE_B;    // 36864
// epilogue psum [4][64][64] f32 = 65536 overlays x/w (ends exactly at 65536)
constexpr int SMEM_PT_OFF   = 65536;                  // pair LUT, 64KB
constexpr int SMEM_LR_OFF   = SMEM_PT_OFF + TO * 256 * 4;   // 131072 (raw LUT rows)
constexpr int SMEM_FLAG_OFF = SMEM_LR_OFF + TO * 16 * 2;    // 133120
constexpr int SMEM_TOTAL    = SMEM_FLAG_OFF + 16;           // 133136

__device__ __half g_x16[BATCH * IN];   // x as fp16

__device__ __forceinline__ void cp_async16(unsigned smem_dst, const void* gmem_src) {
    asm volatile("cp.async.cg.shared.global [%0], [%1], 16;\n" :: "r"(smem_dst), "l"(gmem_src));
}
__device__ __forceinline__ void cp_commit() {
    asm volatile("cp.async.commit_group;\n" ::: "memory");
}
template <int N>
__device__ __forceinline__ void cp_wait() {
    asm volatile("cp.async.wait_group %0;\n" :: "n"(N) : "memory");
}
__device__ __forceinline__ void ldsm_x4(unsigned& r0, unsigned& r1, unsigned& r2, unsigned& r3,
                                        unsigned addr) {
    asm volatile("ldmatrix.sync.aligned.m8n8.x4.shared.b16 {%0,%1,%2,%3}, [%4];\n"
                 : "=r"(r0), "=r"(r1), "=r"(r2), "=r"(r3) : "r"(addr));
}
__device__ __forceinline__ void mma_m16n8k16(float& c0, float& c1, float& c2, float& c3,
                                             unsigned a0, unsigned a1, unsigned a2, unsigned a3,
                                             unsigned b0, unsigned b1) {
    asm volatile(
        "mma.sync.aligned.m16n8k16.row.col.f32.f16.f16.f32 "
        "{%0,%1,%2,%3}, {%4,%5,%6,%7}, {%8,%9}, {%0,%1,%2,%3};\n"
        : "+f"(c0), "+f"(c1), "+f"(c2), "+f"(c3)
        : "r"(a0), "r"(a1), "r"(a2), "r"(a3), "r"(b0), "r"(b1));
}

// probe: lut words as f32 land in (1e-4,1) for N(0,0.05) f32 storage; as packed
// half pairs the f32 reinterpretation is < ~3e-5. Ballot over 32 words.
__device__ __forceinline__ int probe_f32(const unsigned* lut_words, int lane) {
    float a = fabsf(__uint_as_float(lut_words[lane]));
    unsigned m = __ballot_sync(0xffffffffu, a > 1e-4f && a < 1.0f);
    return __popc(m) >= 16;
}

// ---- launch 1: x -> fp16 scratch (probe inline, per block) ----
__global__ void xconv_kernel(const void* __restrict__ xp,
                             const unsigned* __restrict__ lut_words) {
    __shared__ int flag_s;
    const int tid = threadIdx.x;
    if (tid < 32) {
        int f = probe_f32(lut_words, tid);
        if (tid == 0) flag_s = f;
    }
    __syncthreads();
    const int i = (blockIdx.x * blockDim.x + tid) * 4;
    if (flag_s) {
        float4 v = *reinterpret_cast<const float4*>(reinterpret_cast<const float*>(xp) + i);
        *reinterpret_cast<__half2*>(g_x16 + i)     = __floats2half2_rn(v.x, v.y);
        *reinterpret_cast<__half2*>(g_x16 + i + 2) = __floats2half2_rn(v.z, v.w);
    } else {
        *reinterpret_cast<uint2*>(g_x16 + i) =
            *reinterpret_cast<const uint2*>(reinterpret_cast<const __half*>(xp) + i);
    }
}

// ---- launch 2: main ----
__global__ __launch_bounds__(THREADS, 1)
void anyprec_linear_kernel(const int*  __restrict__ qw,
                           const void* __restrict__ lutp,
                           void*       __restrict__ outp) {
    extern __shared__ char smem[];
    unsigned* pt_u   = reinterpret_cast<unsigned*>(smem + SMEM_PT_OFF);
    __half*   lr_s   = reinterpret_cast<__half*>(smem + SMEM_LR_OFF);
    int*      flag_p = reinterpret_cast<int*>(smem + SMEM_FLAG_OFF);
    const unsigned smem_u = (unsigned)__cvta_generic_to_shared(smem);
    const unsigned x_u    = smem_u + SMEM_X_OFF;
    const unsigned w_u    = smem_u + SMEM_W_OFF;

    const int tid  = threadIdx.x;
    const int lane = tid & 31;
    const int wid  = tid >> 5;
    const int rblk = blockIdx.x * TO;

    if (tid < 32) {
        int f = probe_f32(reinterpret_cast<const unsigned*>(lutp), lane);
        if (lane == 0) *flag_p = f;
    }
    __syncthreads();
    const bool F32 = (*flag_p != 0);

    // LUT rows -> smem (as half)
    if (F32) {
        const float* lf = reinterpret_cast<const float*>(lutp);
        for (int i = tid; i < TO * 16; i += THREADS)
            lr_s[i] = __float2half_rn(lf[(size_t)rblk * 16 + i]);
    } else {
        const __half* lh = reinterpret_cast<const __half*>(lutp);
        for (int i = tid; i < TO * 16; i += THREADS)
            lr_s[i] = lh[(size_t)rblk * 16 + i];
    }

    // ---- x prefetch mapping: thread -> (row 0..63, 16B seg 0..7) ----
    const int xr = tid >> 3, x8 = tid & 7;
    const __half* xg_base = g_x16 + (size_t)xr * IN + x8 * 8;
    const unsigned x_dst  = x_u + (xr * XS + x8 * 8) * 2;

    auto xfetch = [&](int c) {
        cp_async16(x_dst + (c & 3) * X_STAGE_B, xg_base + c * KC);
    };

    // ---- qw LDG mapping: thread -> (row 0..63, 8-int seg 0..7) ----
    const int drow = tid >> 3, dseg = tid & 7;
    const int4* qptr = reinterpret_cast<const int4*>(
        qw + (size_t)(rblk + drow) * IN + dseg * 8);   // +c*16 per chunk
    const unsigned w_st = w_u + (drow * WS + dseg * 8) * 2;

    xfetch(0); cp_commit();
    xfetch(1); cp_commit();
    xfetch(2); cp_commit();

    int4 qq0[4], qq1[4];
    qq0[0] = __ldcs(qptr);      qq1[0] = __ldcs(qptr + 1);
    qq0[1] = __ldcs(qptr + 16); qq1[1] = __ldcs(qptr + 17);

    // Build pair LUT: ptab[row][(a<<4)|b] = halves (lut[row][a], lut[row][b])
    __syncthreads();   // lr_s visible
    for (int idx = tid; idx < TO * 256; idx += THREADS) {
        const int row = idx >> 8, pr = idx & 255;
        unsigned lo = __half_as_ushort(lr_s[row * 16 + (pr >> 4)]);
        unsigned hi = __half_as_ushort(lr_s[row * 16 + (pr & 15)]);
        pt_u[idx] = lo | (hi << 16);
    }
    const unsigned* ptrow = pt_u + (drow << 8);

    // ---- warp decomposition: 2m x 2n x 4k ----
    const int mi = wid >> 3, ni = (wid >> 2) & 1, ki = wid & 3;
    const int m_base = mi * 32, n_base = ni * 32, k_base = ki * 16;
    const int q = lane >> 3, r = lane & 7, g = lane >> 2, t = lane & 3;

    unsigned a_off[2], b_off[2];
#pragma unroll
    for (int mt = 0; mt < 2; mt++)
        a_off[mt] = ((m_base + mt * 16 + ((q & 1) << 3) + r) * XS
                     + k_base + ((q >> 1) << 3)) * 2;
#pragma unroll
    for (int nt = 0; nt < 2; nt++)
        b_off[nt] = ((n_base + nt * 16 + ((q >> 1) << 3) + r) * WS
                     + k_base + ((q & 1) << 3)) * 2;

    float acc[2][4][4];
#pragma unroll
    for (int mt = 0; mt < 2; mt++)
#pragma unroll
        for (int j = 0; j < 4; j++)
#pragma unroll
            for (int e = 0; e < 4; e++) acc[mt][j][e] = 0.0f;

#pragma unroll 4
    for (int c = 0; c < NCH; c++) {
        // stream qweight 2 chunks ahead (register ring, indices fold via unroll)
        if (c + 2 < NCH) {
            qq0[(c + 2) & 3] = __ldcs(qptr + (c + 2) * 16);
            qq1[(c + 2) & 3] = __ldcs(qptr + (c + 2) * 16 + 1);
        }

        cp_wait<2>();          // x stage c landed (this thread's part)
        __syncthreads();       // all parts visible; iter c-1 ldsm retired
                               // (first iter: also orders ptab build)
        if (c + 3 < NCH) xfetch(c + 3);
        cp_commit();           // commit every iter keeps wait<2> invariant

        // ---- dequant via pair LUT: 4 LDS.32 + one STS.128 ----
        {
            const int4 qa = qq0[c & 3];
            const int4 qb = qq1[c & 3];
            unsigned p0 = ptrow[((qa.x & 15) << 4) | (qa.y & 15)];
            unsigned p1 = ptrow[((qa.z & 15) << 4) | (qa.w & 15)];
            unsigned p2 = ptrow[((qb.x & 15) << 4) | (qb.y & 15)];
            unsigned p3 = ptrow[((qb.z & 15) << 4) | (qb.w & 15)];
            asm volatile("st.shared.v4.b32 [%0], {%1,%2,%3,%4};" ::
                         "r"(w_st + (c & 1) * W_BUF_B),
                         "r"(p0), "r"(p1), "r"(p2), "r"(p3) : "memory");
        }
        __syncthreads();       // w tile visible

        // ---- mma: 4 ldmatrix.x4 + 8 mma ----
        const unsigned xa = x_u + (c & 3) * X_STAGE_B;
        const unsigned wa = w_u + (c & 1) * W_BUF_B;
        unsigned af[2][4], bf[2][4];
#pragma unroll
        for (int mt = 0; mt < 2; mt++)
            ldsm_x4(af[mt][0], af[mt][1], af[mt][2], af[mt][3], xa + a_off[mt]);
#pragma unroll
        for (int nt = 0; nt < 2; nt++)
            ldsm_x4(bf[nt][0], bf[nt][1], bf[nt][2], bf[nt][3], wa + b_off[nt]);
#pragma unroll
        for (int mt = 0; mt < 2; mt++)
#pragma unroll
            for (int j = 0; j < 4; j++) {
                const int nt = j >> 1, sub = j & 1;
                mma_m16n8k16(acc[mt][j][0], acc[mt][j][1], acc[mt][j][2], acc[mt][j][3],
                             af[mt][0], af[mt][1], af[mt][2], af[mt][3],
                             bf[nt][sub * 2], bf[nt][sub * 2 + 1]);
            }
    }

    // ---- epilogue: k-split reduction via smem psum (overlays x/w) ----
    __syncthreads();
    float* psum = reinterpret_cast<float*>(smem);   // [4][64][64]
#pragma unroll
    for (int mt = 0; mt < 2; mt++)
#pragma unroll
        for (int j = 0; j < 4; j++) {
            const int m = m_base + mt * 16 + g;
            const int n = n_base + j * 8 + t * 2;
            *reinterpret_cast<float2*>(psum + ki * 4096 + m * 64 + n) =
                make_float2(acc[mt][j][0], acc[mt][j][1]);
            *reinterpret_cast<float2*>(psum + ki * 4096 + (m + 8) * 64 + n) =
                make_float2(acc[mt][j][2], acc[mt][j][3]);
        }
    __syncthreads();

    {
        const int base = tid * 8;          // 512 threads x 8 outputs = 64x64
        const int m = base >> 6;
        const int n0 = base & 63;
#pragma unroll
        for (int e = 0; e < 8; e++) {
            const int n = n0 + e;
            float s = psum[m * 64 + n] + psum[4096 + m * 64 + n]
                    + psum[8192 + m * 64 + n] + psum[12288 + m * 64 + n];
            if (F32) {
                reinterpret_cast<float*>(outp)[(size_t)m * OUT + rblk + n] =
                    __half2float(__float2half_rn(s));
            } else {
                reinterpret_cast<__half*>(outp)[(size_t)m * OUT + rblk + n] =
                    __float2half_rn(s);
            }
        }
    }
}

extern "C" void kernel_launch(void* const* d_in, const int* in_sizes, int n_in,
                              void* d_out, int out_size) {
    // Identify inputs by element count: x 524288, qweight 67108864, lut 131072
    const void* x = nullptr; const int* qw = nullptr; const void* lut = nullptr;
    for (int i = 0; i < n_in; i++) {
        if (in_sizes[i] == BATCH * IN)     x   = d_in[i];
        else if (in_sizes[i] == OUT * IN)  qw  = (const int*)d_in[i];
        else if (in_sizes[i] == OUT * 16)  lut = d_in[i];
    }

    cudaFuncSetAttribute(anyprec_linear_kernel,
                         cudaFuncAttributeMaxDynamicSharedMemorySize, SMEM_TOTAL);

    xconv_kernel<<<BATCH * IN / 4 / 256, 256>>>(x, reinterpret_cast<const unsigned*>(lut));
    anyprec_linear_kernel<<<OUT / TO, THREADS, SMEM_TOTAL>>>(qw, lut, d_out);
}

// round 11
// speedup vs baseline: 1.1728x; 1.0454x over previous
#include <cuda_runtime.h>
#include <cuda_fp16.h>
#include <cstdint>

// Problem constants
constexpr int BATCH = 64;
constexpr int IN    = 8192;
constexpr int OUT   = 8192;

// Tiling: CTA = 64 out rows x full K, grid 128.
constexpr int TO      = 64;
constexpr int KC      = 64;
constexpr int NCH     = IN / KC;     // 128
constexpr int THREADS = 512;         // 16 warps: 2m x 2n x 4k

constexpr int XS = 72;               // x smem stride (halves) - conflict-free ldsm
constexpr int WS = 72;               // w smem stride (halves)

constexpr int X_STAGE_B = TO * XS * 2;            // 9216 B
constexpr int W_BUF_B   = TO * WS * 2;            // 9216 B
constexpr int X_STAGES  = 4;

constexpr int SMEM_X_OFF   = 0;
constexpr int SMEM_W_OFF   = X_STAGES * X_STAGE_B;    // 36864
// epilogue psum [4][64][64] f32 = 65536 overlays x/w; lut+flag live above it
constexpr int SMEM_LUT_OFF  = 65536;
constexpr int SMEM_FLAG_OFF = SMEM_LUT_OFF + TO * 16 * 2;  // 67584
constexpr int SMEM_TOTAL    = 67840;

__device__ __half g_x16[BATCH * IN];   // x as fp16

__device__ __forceinline__ void cp_async16(unsigned smem_dst, const void* gmem_src) {
    asm volatile("cp.async.cg.shared.global [%0], [%1], 16;\n" :: "r"(smem_dst), "l"(gmem_src));
}
__device__ __forceinline__ void cp_commit() {
    asm volatile("cp.async.commit_group;\n" ::: "memory");
}
template <int N>
__device__ __forceinline__ void cp_wait() {
    asm volatile("cp.async.wait_group %0;\n" :: "n"(N) : "memory");
}
__device__ __forceinline__ void ldsm_x4(unsigned& r0, unsigned& r1, unsigned& r2, unsigned& r3,
                                        unsigned addr) {
    asm volatile("ldmatrix.sync.aligned.m8n8.x4.shared.b16 {%0,%1,%2,%3}, [%4];\n"
                 : "=r"(r0), "=r"(r1), "=r"(r2), "=r"(r3) : "r"(addr));
}
__device__ __forceinline__ void mma_m16n8k16(float& c0, float& c1, float& c2, float& c3,
                                             unsigned a0, unsigned a1, unsigned a2, unsigned a3,
                                             unsigned b0, unsigned b1) {
    asm volatile(
        "mma.sync.aligned.m16n8k16.row.col.f32.f16.f16.f32 "
        "{%0,%1,%2,%3}, {%4,%5,%6,%7}, {%8,%9}, {%0,%1,%2,%3};\n"
        : "+f"(c0), "+f"(c1), "+f"(c2), "+f"(c3)
        : "r"(a0), "r"(a1), "r"(a2), "r"(a3), "r"(b0), "r"(b1));
}

// probe: lut words as f32 land in (1e-4,1) for N(0,0.05) f32 storage; as packed
// half pairs the f32 reinterpretation is < ~3e-5. Ballot over 32 words.
__device__ __forceinline__ int probe_f32(const unsigned* lut_words, int lane) {
    float a = fabsf(__uint_as_float(lut_words[lane]));
    unsigned m = __ballot_sync(0xffffffffu, a > 1e-4f && a < 1.0f);
    return __popc(m) >= 16;
}

// ---- launch 1: x -> fp16 scratch (probe inline, per block) ----
__global__ void xconv_kernel(const void* __restrict__ xp,
                             const unsigned* __restrict__ lut_words) {
    __shared__ int flag_s;
    const int tid = threadIdx.x;
    if (tid < 32) {
        int f = probe_f32(lut_words, tid);
        if (tid == 0) flag_s = f;
    }
    __syncthreads();
    const int i = (blockIdx.x * blockDim.x + tid) * 4;
    if (flag_s) {
        float4 v = *reinterpret_cast<const float4*>(reinterpret_cast<const float*>(xp) + i);
        *reinterpret_cast<__half2*>(g_x16 + i)     = __floats2half2_rn(v.x, v.y);
        *reinterpret_cast<__half2*>(g_x16 + i + 2) = __floats2half2_rn(v.z, v.w);
    } else {
        *reinterpret_cast<uint2*>(g_x16 + i) =
            *reinterpret_cast<const uint2*>(reinterpret_cast<const __half*>(xp) + i);
    }
}

// ---- launch 2: main ----
__global__ __launch_bounds__(THREADS, 1)
void anyprec_linear_kernel(const int*  __restrict__ qw,
                           const void* __restrict__ lutp,
                           void*       __restrict__ outp) {
    extern __shared__ char smem[];
    __half* lut_s  = reinterpret_cast<__half*>(smem + SMEM_LUT_OFF);
    int*    flag_p = reinterpret_cast<int*>(smem + SMEM_FLAG_OFF);
    const unsigned smem_u = (unsigned)__cvta_generic_to_shared(smem);
    const unsigned x_u    = smem_u + SMEM_X_OFF;
    const unsigned w_u    = smem_u + SMEM_W_OFF;

    const int tid  = threadIdx.x;
    const int lane = tid & 31;
    const int wid  = tid >> 5;
    const int rblk = blockIdx.x * TO;

    if (tid < 32) {
        int f = probe_f32(reinterpret_cast<const unsigned*>(lutp), lane);
        if (lane == 0) *flag_p = f;
    }
    __syncthreads();
    const bool F32 = (*flag_p != 0);

    // LUT rows -> smem (as half)
    if (F32) {
        const float* lf = reinterpret_cast<const float*>(lutp);
        for (int i = tid; i < TO * 16; i += THREADS)
            lut_s[i] = __float2half_rn(lf[(size_t)rblk * 16 + i]);
    } else {
        const __half* lh = reinterpret_cast<const __half*>(lutp);
        for (int i = tid; i < TO * 16; i += THREADS)
            lut_s[i] = lh[(size_t)rblk * 16 + i];
    }

    // ---- x prefetch mapping: thread -> (row 0..63, 16B seg 0..7) ----
    const int xr = tid >> 3, x8 = tid & 7;
    const __half* xg_base = g_x16 + (size_t)xr * IN + x8 * 8;
    const unsigned x_dst  = x_u + (xr * XS + x8 * 8) * 2;

    auto xfetch = [&](int c) {
        cp_async16(x_dst + (c & 3) * X_STAGE_B, xg_base + c * KC);
    };

    // ---- qw LDG mapping: thread -> (row 0..63, 8-int seg 0..7) ----
    const int drow = tid >> 3, dseg = tid & 7;
    const int4* qptr = reinterpret_cast<const int4*>(
        qw + (size_t)(rblk + drow) * IN + dseg * 8);   // +c*16 per chunk
    const __half* lrow = lut_s + drow * 16;
    const unsigned w_st = w_u + (drow * WS + dseg * 8) * 2;

    xfetch(0); cp_commit();
    xfetch(1); cp_commit();
    xfetch(2); cp_commit();

    // qweight register ring: 4 chunks deep
    int4 qq0[4], qq1[4];
    qq0[0] = __ldcs(qptr);      qq1[0] = __ldcs(qptr + 1);
    qq0[1] = __ldcs(qptr + 16); qq1[1] = __ldcs(qptr + 17);
    qq0[2] = __ldcs(qptr + 32); qq1[2] = __ldcs(qptr + 33);

    // dequant helper: chunk cd -> wbuf[cd&1]
    auto dequant = [&](int cd) {
        const int4 qa = qq0[cd & 3];
        const int4 qb = qq1[cd & 3];
        __half2 h0 = __halves2half2(lrow[qa.x & 15], lrow[qa.y & 15]);
        __half2 h1 = __halves2half2(lrow[qa.z & 15], lrow[qa.w & 15]);
        __half2 h2 = __halves2half2(lrow[qb.x & 15], lrow[qb.y & 15]);
        __half2 h3 = __halves2half2(lrow[qb.z & 15], lrow[qb.w & 15]);
        asm volatile("st.shared.v4.b32 [%0], {%1,%2,%3,%4};" ::
                     "r"(w_st + (cd & 1) * W_BUF_B),
                     "r"(*reinterpret_cast<unsigned*>(&h0)),
                     "r"(*reinterpret_cast<unsigned*>(&h1)),
                     "r"(*reinterpret_cast<unsigned*>(&h2)),
                     "r"(*reinterpret_cast<unsigned*>(&h3)) : "memory");
    };

    // ---- warp decomposition: 2m x 2n x 4k ----
    const int mi = wid >> 3, ni = (wid >> 2) & 1, ki = wid & 3;
    const int m_base = mi * 32, n_base = ni * 32, k_base = ki * 16;
    const int q = lane >> 3, r = lane & 7, g = lane >> 2, t = lane & 3;

    unsigned a_off[2], b_off[2];
#pragma unroll
    for (int mt = 0; mt < 2; mt++)
        a_off[mt] = ((m_base + mt * 16 + ((q & 1) << 3) + r) * XS
                     + k_base + ((q >> 1) << 3)) * 2;
#pragma unroll
    for (int nt = 0; nt < 2; nt++)
        b_off[nt] = ((n_base + nt * 16 + ((q >> 1) << 3) + r) * WS
                     + k_base + ((q & 1) << 3)) * 2;

    float acc[2][4][4];
#pragma unroll
    for (int mt = 0; mt < 2; mt++)
#pragma unroll
        for (int j = 0; j < 4; j++)
#pragma unroll
            for (int e = 0; e < 4; e++) acc[mt][j][e] = 0.0f;

    // ---- prologue: dequant chunk 0 into wbuf0 (lut_s visible after syncthreads) ----
    __syncthreads();
    dequant(0);

    // ---- main loop: 1 barrier per chunk; dequant(c+1) overlaps mma(c) ----
#pragma unroll 4
    for (int c = 0; c < NCH; c++) {
        // stream qweight 3 chunks ahead of dequant target (ring depth 4)
        if (c + 3 < NCH) {
            qq0[(c + 3) & 3] = __ldcs(qptr + (c + 3) * 16);
            qq1[(c + 3) & 3] = __ldcs(qptr + (c + 3) * 16 + 1);
        }

        cp_wait<2>();          // x stage c landed (this thread's part)
        __syncthreads();       // all STS for wbuf[c&1] + all x[c] parts visible;
                               // also retires ldsm of chunk c-1 before we overwrite
        if (c + 3 < NCH) xfetch(c + 3);
        cp_commit();           // commit every iter keeps wait<2> invariant

        // ---- ldsm for chunk c (issue first; mma waits on these) ----
        const unsigned xa = x_u + (c & 3) * X_STAGE_B;
        const unsigned wa = w_u + (c & 1) * W_BUF_B;
        unsigned af[2][4], bf[2][4];
#pragma unroll
        for (int mt = 0; mt < 2; mt++)
            ldsm_x4(af[mt][0], af[mt][1], af[mt][2], af[mt][3], xa + a_off[mt]);
#pragma unroll
        for (int nt = 0; nt < 2; nt++)
            ldsm_x4(bf[nt][0], bf[nt][1], bf[nt][2], bf[nt][3], wa + b_off[nt]);

        // ---- dequant chunk c+1 (independent; retires under mma shadow) ----
        if (c + 1 < NCH) dequant(c + 1);

        // ---- mma chunk c ----
#pragma unroll
        for (int mt = 0; mt < 2; mt++)
#pragma unroll
            for (int j = 0; j < 4; j++) {
                const int nt = j >> 1, sub = j & 1;
                mma_m16n8k16(acc[mt][j][0], acc[mt][j][1], acc[mt][j][2], acc[mt][j][3],
                             af[mt][0], af[mt][1], af[mt][2], af[mt][3],
                             bf[nt][sub * 2], bf[nt][sub * 2 + 1]);
            }
    }

    // ---- epilogue: k-split reduction via smem psum (overlays x/w) ----
    __syncthreads();
    float* psum = reinterpret_cast<float*>(smem);   // [4][64][64]
#pragma unroll
    for (int mt = 0; mt < 2; mt++)
#pragma unroll
        for (int j = 0; j < 4; j++) {
            const int m = m_base + mt * 16 + g;
            const int n = n_base + j * 8 + t * 2;
            *reinterpret_cast<float2*>(psum + ki * 4096 + m * 64 + n) =
                make_float2(acc[mt][j][0], acc[mt][j][1]);
            *reinterpret_cast<float2*>(psum + ki * 4096 + (m + 8) * 64 + n) =
                make_float2(acc[mt][j][2], acc[mt][j][3]);
        }
    __syncthreads();

    {
        const int base = tid * 8;          // 512 threads x 8 outputs = 64x64
        const int m = base >> 6;
        const int n0 = base & 63;
#pragma unroll
        for (int e = 0; e < 8; e++) {
            const int n = n0 + e;
            float s = psum[m * 64 + n] + psum[4096 + m * 64 + n]
                    + psum[8192 + m * 64 + n] + psum[12288 + m * 64 + n];
            if (F32) {
                reinterpret_cast<float*>(outp)[(size_t)m * OUT + rblk + n] =
                    __half2float(__float2half_rn(s));
            } else {
                reinterpret_cast<__half*>(outp)[(size_t)m * OUT + rblk + n] =
                    __float2half_rn(s);
            }
        }
    }
}

extern "C" void kernel_launch(void* const* d_in, const int* in_sizes, int n_in,
                              void* d_out, int out_size) {
    // Identify inputs by element count: x 524288, qweight 67108864, lut 131072
    const void* x = nullptr; const int* qw = nullptr; const void* lut = nullptr;
    for (int i = 0; i < n_in; i++) {
        if (in_sizes[i] == BATCH * IN)     x   = d_in[i];
        else if (in_sizes[i] == OUT * IN)  qw  = (const int*)d_in[i];
        else if (in_sizes[i] == OUT * 16)  lut = d_in[i];
    }

    cudaFuncSetAttribute(anyprec_linear_kernel,
                         cudaFuncAttributeMaxDynamicSharedMemorySize, SMEM_TOTAL);

    xconv_kernel<<<BATCH * IN / 4 / 256, 256>>>(x, reinterpret_cast<const unsigned*>(lut));
    anyprec_linear_kernel<<<OUT / TO, THREADS, SMEM_TOTAL>>>(qw, lut, d_out);
}